// round 1
// baseline (speedup 1.0000x reference)
#include <cuda_runtime.h>
#include <math_constants.h>

// Flash-attention baseline, fp32 FFMA, sm_103a.
// B=4, Lq=Lk=4096, D=64. scores = Q K^T (no scaling), softmax, O = P V.
//
// CTA: 64 query rows. 256 threads as 16x16 grid (tx = tid&15, ty = tid>>4).
// S tile per thread: rows {ty+16i}, cols {tx+16j} (strided -> conflict-free
// float4 K reads with stride-68 padding). O tile per thread: rows {ty+16i},
// cols {4tx..4tx+3} (contiguous -> vectorized V reads + coalesced stores).

#define BM 64
#define BN 64
#define HD 64
#define KSTRIDE 68      // padded row stride for K/P buffer (word-stride 17, odd)
#define NTHREADS 256

__global__ __launch_bounds__(NTHREADS, 2)
void attn_kernel(const float* __restrict__ Q, const float* __restrict__ K,
                 const float* __restrict__ V, float* __restrict__ O,
                 int Lq, int Lk)
{
    extern __shared__ float sm[];
    float* Qs = sm;                          // [BM][HD]
    float* Vs = sm + BM * HD;                // [BN][HD]
    float* KP = sm + BM * HD + BN * HD;      // [BN][KSTRIDE], reused as P[BM][KSTRIDE]

    const int tid  = threadIdx.x;
    const int tx   = tid & 15;
    const int ty   = tid >> 4;
    const int b    = blockIdx.y;
    const int row0 = blockIdx.x * BM;

    const float* Qb = Q + (size_t)b * Lq * HD;
    const float* Kb = K + (size_t)b * Lk * HD;
    const float* Vb = V + (size_t)b * Lk * HD;
    float*       Ob = O + (size_t)b * Lq * HD;

    // Load Q tile (once per CTA), coalesced float4.
#pragma unroll
    for (int p = 0; p < (BM * HD) / (NTHREADS * 4); ++p) {
        int idx = (p * NTHREADS + tid) * 4;
        *(float4*)&Qs[idx] = *(const float4*)&Qb[(size_t)row0 * HD + idx];
    }

    float o[4][4];
    float m[4], l[4];
#pragma unroll
    for (int i = 0; i < 4; i++) {
        m[i] = -CUDART_INF_F;
        l[i] = 0.f;
#pragma unroll
        for (int j = 0; j < 4; j++) o[i][j] = 0.f;
    }

    for (int t0 = 0; t0 < Lk; t0 += BN) {
        // Load K tile (into padded KP) and V tile (natural layout), coalesced.
#pragma unroll
        for (int p = 0; p < (BN * HD) / (NTHREADS * 4); ++p) {
            int idx = (p * NTHREADS + tid) * 4;     // 0..4095, step 4
            int c = idx >> 6;                        // row within tile
            int k = idx & 63;                        // col (16B aligned)
            *(float4*)&KP[c * KSTRIDE + k] = *(const float4*)&Kb[(size_t)t0 * HD + idx];
            *(float4*)&Vs[idx]             = *(const float4*)&Vb[(size_t)t0 * HD + idx];
        }
        __syncthreads();

        // S = Q K^T  (4x4 per thread, k unrolled by 4 with float4 smem reads)
        float s[4][4];
#pragma unroll
        for (int i = 0; i < 4; i++)
#pragma unroll
            for (int j = 0; j < 4; j++) s[i][j] = 0.f;

#pragma unroll
        for (int k4 = 0; k4 < HD; k4 += 4) {
            float4 qf[4], kf[4];
#pragma unroll
            for (int i = 0; i < 4; i++)
                qf[i] = *(const float4*)&Qs[(ty + 16 * i) * HD + k4];
#pragma unroll
            for (int j = 0; j < 4; j++)
                kf[j] = *(const float4*)&KP[(tx + 16 * j) * KSTRIDE + k4];
#pragma unroll
            for (int i = 0; i < 4; i++)
#pragma unroll
                for (int j = 0; j < 4; j++) {
                    s[i][j] = fmaf(qf[i].x, kf[j].x, s[i][j]);
                    s[i][j] = fmaf(qf[i].y, kf[j].y, s[i][j]);
                    s[i][j] = fmaf(qf[i].z, kf[j].z, s[i][j]);
                    s[i][j] = fmaf(qf[i].w, kf[j].w, s[i][j]);
                }
        }

        // Online softmax. Row r is owned by the 16 threads sharing ty
        // (lanes [0,16) or [16,32) of a warp) -> butterfly shuffle width 16.
#pragma unroll
        for (int i = 0; i < 4; i++) {
            float mt = fmaxf(fmaxf(s[i][0], s[i][1]), fmaxf(s[i][2], s[i][3]));
#pragma unroll
            for (int d = 1; d < 16; d <<= 1)
                mt = fmaxf(mt, __shfl_xor_sync(0xffffffffu, mt, d));
            float mn   = fmaxf(m[i], mt);
            float corr = __expf(m[i] - mn);
            m[i] = mn;
            float rs = 0.f;
#pragma unroll
            for (int j = 0; j < 4; j++) {
                s[i][j] = __expf(s[i][j] - mn);
                rs += s[i][j];
            }
#pragma unroll
            for (int d = 1; d < 16; d <<= 1)
                rs += __shfl_xor_sync(0xffffffffu, rs, d);
            l[i] = l[i] * corr + rs;
#pragma unroll
            for (int j = 0; j < 4; j++) o[i][j] *= corr;
        }

        __syncthreads();   // everyone done reading K tile
        // Write P into the K buffer: P[r][c] at stride KSTRIDE.
#pragma unroll
        for (int i = 0; i < 4; i++)
#pragma unroll
            for (int j = 0; j < 4; j++)
                KP[(ty + 16 * i) * KSTRIDE + (tx + 16 * j)] = s[i][j];
        __syncthreads();

        // O += P V   (reduction over c; P broadcast reads, V float4 reads)
#pragma unroll 4
        for (int c = 0; c < BN; ++c) {
            float4 vf = *(const float4*)&Vs[c * HD + 4 * tx];
            float pr[4];
#pragma unroll
            for (int i = 0; i < 4; i++)
                pr[i] = KP[(ty + 16 * i) * KSTRIDE + c];
#pragma unroll
            for (int i = 0; i < 4; i++) {
                o[i][0] = fmaf(pr[i], vf.x, o[i][0]);
                o[i][1] = fmaf(pr[i], vf.y, o[i][1]);
                o[i][2] = fmaf(pr[i], vf.z, o[i][2]);
                o[i][3] = fmaf(pr[i], vf.w, o[i][3]);
            }
        }
        __syncthreads();   // before next tile overwrites KP/Vs
    }

    // Epilogue: normalize and store (float4, coalesced).
#pragma unroll
    for (int i = 0; i < 4; i++) {
        float inv = 1.0f / l[i];
        float4 r;
        r.x = o[i][0] * inv;
        r.y = o[i][1] * inv;
        r.z = o[i][2] * inv;
        r.w = o[i][3] * inv;
        *(float4*)&Ob[(size_t)(row0 + ty + 16 * i) * HD + 4 * tx] = r;
    }
}

extern "C" void kernel_launch(void* const* d_in, const int* in_sizes, int n_in,
                              void* d_out, int out_size)
{
    const float* Q = (const float*)d_in[0];
    const float* K = (const float*)d_in[1];
    const float* V = (const float*)d_in[2];
    float*       O = (float*)d_out;

    const int B  = 4;
    const int Lq = 4096;
    const int Lk = 4096;

    const size_t smem = (size_t)(BM * HD + BN * HD + BN * KSTRIDE) * sizeof(float); // 50176 B
    cudaFuncSetAttribute(attn_kernel, cudaFuncAttributeMaxDynamicSharedMemorySize, (int)smem);

    dim3 grid(Lq / BM, B);
    attn_kernel<<<grid, NTHREADS, smem>>>(Q, K, V, O, Lq, Lk);
}

// round 4
// speedup vs baseline: 4.4738x; 4.4738x over previous
#include <cuda_runtime.h>
#include <cuda_fp16.h>
#include <cstdint>

// ============================================================================
// Flash attention via mma.sync.m16n8k16 (fp16 in, fp32 accum), sm_103 base ISA.
// B=4, L=4096, D=64.  S = Q K^T in 3xFP16 (compensated), online softmax,
// O = P V in fp16 single-pass.  Prepass converts fp32 -> fp16 hi/resid once.
// ============================================================================

#define LSEQ 4096
#define BATCH 4
#define HD 64
#define BM 128
#define BN 64
#define NTILES (LSEQ / BN)     // 64
#define NTHREADS 256
#define QSTR 72                // padded smem row stride (halfs): conflict-free ldmatrix
#define KSTR 72

// smem layout (half indices)
#define QH_S 0
#define QR_S (128 * QSTR)                 // 9216
#define BUF_S (2 * 128 * QSTR)            // 18432
#define BUF_HALFS (3 * BN * KSTR)         // 13824 per buffer (kh, kr, vh)
#define KH_OFF 0
#define KR_OFF (BN * KSTR)
#define VH_OFF (2 * BN * KSTR)
#define SMEM_BYTES ((BUF_S + 2 * BUF_HALFS) * 2)   // 92160 B

// fp16 scratch (converted once per run by prep_kernel)
__device__ __align__(16) __half g_qh[BATCH * LSEQ * HD];
__device__ __align__(16) __half g_qr[BATCH * LSEQ * HD];
__device__ __align__(16) __half g_kh[BATCH * LSEQ * HD];
__device__ __align__(16) __half g_kr[BATCH * LSEQ * HD];
__device__ __align__(16) __half g_vh[BATCH * LSEQ * HD];

// ---------------------------------------------------------------------------
// helpers
// ---------------------------------------------------------------------------
__device__ __forceinline__ uint32_t smem_u32(const void* p) {
    uint32_t a;
    asm("{ .reg .u64 t; cvta.to.shared.u64 t, %1; cvt.u32.u64 %0, t; }" : "=r"(a) : "l"(p));
    return a;
}
__device__ __forceinline__ void cp16(uint32_t dst, const void* src) {
    asm volatile("cp.async.ca.shared.global [%0], [%1], 16;" :: "r"(dst), "l"(src));
}
#define CP_COMMIT() asm volatile("cp.async.commit_group;" ::: "memory")
#define CP_WAIT(n)  asm volatile("cp.async.wait_group %0;" :: "n"(n) : "memory")

__device__ __forceinline__ void ldsm4(uint32_t addr, uint32_t& r0, uint32_t& r1,
                                      uint32_t& r2, uint32_t& r3) {
    asm volatile("ldmatrix.sync.aligned.m8n8.x4.shared.b16 {%0,%1,%2,%3}, [%4];"
                 : "=r"(r0), "=r"(r1), "=r"(r2), "=r"(r3) : "r"(addr));
}
__device__ __forceinline__ void ldsm4t(uint32_t addr, uint32_t& r0, uint32_t& r1,
                                       uint32_t& r2, uint32_t& r3) {
    asm volatile("ldmatrix.sync.aligned.m8n8.x4.trans.shared.b16 {%0,%1,%2,%3}, [%4];"
                 : "=r"(r0), "=r"(r1), "=r"(r2), "=r"(r3) : "r"(addr));
}
__device__ __forceinline__ void mma16816(float* c, const uint32_t* a, const uint32_t* b) {
    asm volatile("mma.sync.aligned.m16n8k16.row.col.f32.f16.f16.f32 "
                 "{%0,%1,%2,%3}, {%4,%5,%6,%7}, {%8,%9}, {%0,%1,%2,%3};"
                 : "+f"(c[0]), "+f"(c[1]), "+f"(c[2]), "+f"(c[3])
                 : "r"(a[0]), "r"(a[1]), "r"(a[2]), "r"(a[3]), "r"(b[0]), "r"(b[1]));
}
__device__ __forceinline__ uint32_t packh(__half a, __half b) {
    __half2 h = __halves2half2(a, b);
    return *(uint32_t*)&h;
}
__device__ __forceinline__ uint32_t pack2f(float a, float b) {
    __half2 h = __floats2half2_rn(a, b);
    return *(uint32_t*)&h;
}

// ---------------------------------------------------------------------------
// prepass: fp32 -> fp16 high + residual (Q, K), fp16 (V)
// ---------------------------------------------------------------------------
__global__ void prep_kernel(const float4* __restrict__ Q, const float4* __restrict__ K,
                            const float4* __restrict__ V) {
    int i = blockIdx.x * blockDim.x + threadIdx.x;   // float4 index
    float4 q = Q[i], k = K[i], v = V[i];

    __half qhx = __float2half_rn(q.x), qhy = __float2half_rn(q.y),
           qhz = __float2half_rn(q.z), qhw = __float2half_rn(q.w);
    __half qrx = __float2half_rn(q.x - __half2float(qhx)),
           qry = __float2half_rn(q.y - __half2float(qhy)),
           qrz = __float2half_rn(q.z - __half2float(qhz)),
           qrw = __float2half_rn(q.w - __half2float(qhw));
    ((uint2*)g_qh)[i] = make_uint2(packh(qhx, qhy), packh(qhz, qhw));
    ((uint2*)g_qr)[i] = make_uint2(packh(qrx, qry), packh(qrz, qrw));

    __half khx = __float2half_rn(k.x), khy = __float2half_rn(k.y),
           khz = __float2half_rn(k.z), khw = __float2half_rn(k.w);
    __half krx = __float2half_rn(k.x - __half2float(khx)),
           kry = __float2half_rn(k.y - __half2float(khy)),
           krz = __float2half_rn(k.z - __half2float(khz)),
           krw = __float2half_rn(k.w - __half2float(khw));
    ((uint2*)g_kh)[i] = make_uint2(packh(khx, khy), packh(khz, khw));
    ((uint2*)g_kr)[i] = make_uint2(packh(krx, kry), packh(krz, krw));

    ((uint2*)g_vh)[i] = make_uint2(pack2f(v.x, v.y), pack2f(v.z, v.w));
}

// ---------------------------------------------------------------------------
// main kernel
// ---------------------------------------------------------------------------
__device__ __forceinline__ void issue_tile(uint32_t smb, int buf, int t, int tid,
                                           const __half* kh_g, const __half* kr_g,
                                           const __half* vh_g) {
    const int base = BUF_S + buf * BUF_HALFS;
    const __half* ks = kh_g + (size_t)t * BN * HD;
    const __half* rs = kr_g + (size_t)t * BN * HD;
    const __half* vs = vh_g + (size_t)t * BN * HD;
#pragma unroll
    for (int i = 0; i < 2; i++) {
        int cid = tid + i * NTHREADS;          // 0..511
        int r = cid >> 3, c = cid & 7;
        uint32_t d = (uint32_t)(r * KSTR * 2 + c * 16);
        const size_t so = (size_t)r * HD + c * 8;
        cp16(smb + (uint32_t)(base + KH_OFF) * 2 + d, ks + so);
        cp16(smb + (uint32_t)(base + KR_OFF) * 2 + d, rs + so);
        cp16(smb + (uint32_t)(base + VH_OFF) * 2 + d, vs + so);
    }
}

__global__ __launch_bounds__(NTHREADS, 1)
void attn_mma(float* __restrict__ O) {
    extern __shared__ __half sh[];
    const uint32_t smb = smem_u32(sh);
    const int tid = threadIdx.x, lane = tid & 31, wid = tid >> 5;
    const int g = lane >> 2, tg = lane & 3;
    const int wr0 = wid * 16;
    const int b = blockIdx.y, row0 = blockIdx.x * BM;

    const __half* qh_g = g_qh + (size_t)(b * LSEQ + row0) * HD;
    const __half* qr_g = g_qr + (size_t)(b * LSEQ + row0) * HD;
    const __half* kh_g = g_kh + (size_t)b * LSEQ * HD;
    const __half* kr_g = g_kr + (size_t)b * LSEQ * HD;
    const __half* vh_g = g_vh + (size_t)b * LSEQ * HD;
    float* Ob = O + (size_t)(b * LSEQ + row0) * HD;

    // Q tiles -> smem (async)
#pragma unroll
    for (int i = 0; i < 4; i++) {
        int cid = tid + i * NTHREADS;          // 0..1023
        int r = cid >> 3, c = cid & 7;
        const size_t so = (size_t)r * HD + c * 8;
        cp16(smb + (uint32_t)(QH_S + r * QSTR) * 2 + c * 16, qh_g + so);
        cp16(smb + (uint32_t)(QR_S + r * QSTR) * 2 + c * 16, qr_g + so);
    }
    CP_COMMIT();
    issue_tile(smb, 0, 0, tid, kh_g, kr_g, vh_g);
    CP_COMMIT();
    CP_WAIT(0);
    __syncthreads();

    // Q fragments -> registers (resident for the whole kernel)
    uint32_t qh[4][4], qr[4][4];
    {
        const int arow = wr0 + (lane & 15);
        const int koff = (lane >> 4) << 3;
#pragma unroll
        for (int s = 0; s < 4; s++) {
            uint32_t a1 = smb + (uint32_t)(QH_S + arow * QSTR + 16 * s + koff) * 2;
            uint32_t a2 = smb + (uint32_t)(QR_S + arow * QSTR + 16 * s + koff) * 2;
            ldsm4(a1, qh[s][0], qh[s][1], qh[s][2], qh[s][3]);
            ldsm4(a2, qr[s][0], qr[s][1], qr[s][2], qr[s][3]);
        }
    }

    float o_[8][4];
#pragma unroll
    for (int j = 0; j < 8; j++)
#pragma unroll
        for (int q = 0; q < 4; q++) o_[j][q] = 0.f;
    float m0 = -1e30f, m1 = -1e30f, l0 = 0.f, l1 = 0.f;

    // per-lane ldmatrix source offsets (within a buffer, halfs)
    const int krow_off = (lane & 7) + ((lane >> 4) << 3);   // + 16*jj
    const int kcol_off = (lane & 8);                        // + 16*s
    const int vkey_off = (lane & 7) + (lane & 8);           // + 16*s
    const int vcol_off = (lane >> 4) << 3;                  // + 16*jj

    for (int t = 0; t < NTILES; t++) {
        __syncthreads();   // all warps done reading buf[(t+1)&1] from iter t-1
        if (t + 1 < NTILES) {
            issue_tile(smb, (t + 1) & 1, t + 1, tid, kh_g, kr_g, vh_g);
            CP_COMMIT();
            CP_WAIT(1);
        } else {
            CP_WAIT(0);
        }
        __syncthreads();   // tile t visible to all

        const uint32_t kb = (uint32_t)(BUF_S + (t & 1) * BUF_HALFS);

        // ---- S = Q K^T (3xFP16) ----
        float s_[8][4];
#pragma unroll
        for (int j = 0; j < 8; j++)
#pragma unroll
            for (int q = 0; q < 4; q++) s_[j][q] = 0.f;

#pragma unroll
        for (int s = 0; s < 4; s++) {
            uint32_t bb[8][2];
#pragma unroll
            for (int jj = 0; jj < 4; jj++) {
                uint32_t addr = smb + (kb + KH_OFF + (uint32_t)((16 * jj + krow_off) * KSTR
                                       + 16 * s + kcol_off)) * 2;
                ldsm4(addr, bb[2 * jj][0], bb[2 * jj][1], bb[2 * jj + 1][0], bb[2 * jj + 1][1]);
            }
#pragma unroll
            for (int j = 0; j < 8; j++) {
                mma16816(s_[j], qh[s], bb[j]);
                mma16816(s_[j], qr[s], bb[j]);
            }
#pragma unroll
            for (int jj = 0; jj < 4; jj++) {
                uint32_t addr = smb + (kb + KR_OFF + (uint32_t)((16 * jj + krow_off) * KSTR
                                       + 16 * s + kcol_off)) * 2;
                ldsm4(addr, bb[2 * jj][0], bb[2 * jj][1], bb[2 * jj + 1][0], bb[2 * jj + 1][1]);
            }
#pragma unroll
            for (int j = 0; j < 8; j++) mma16816(s_[j], qh[s], bb[j]);
        }

        // ---- online softmax (fully in-warp; rows g and g+8 of this warp) ----
        float m0t = s_[0][0], m1t = s_[0][2];
#pragma unroll
        for (int j = 0; j < 8; j++) {
            m0t = fmaxf(m0t, fmaxf(s_[j][0], s_[j][1]));
            m1t = fmaxf(m1t, fmaxf(s_[j][2], s_[j][3]));
        }
        m0t = fmaxf(m0t, __shfl_xor_sync(0xffffffffu, m0t, 1));
        m0t = fmaxf(m0t, __shfl_xor_sync(0xffffffffu, m0t, 2));
        m1t = fmaxf(m1t, __shfl_xor_sync(0xffffffffu, m1t, 1));
        m1t = fmaxf(m1t, __shfl_xor_sync(0xffffffffu, m1t, 2));
        const float m0n = fmaxf(m0, m0t), m1n = fmaxf(m1, m1t);
        const float c0 = __expf(m0 - m0n), c1 = __expf(m1 - m1n);
        m0 = m0n; m1 = m1n;

        uint32_t pa[4][4];
        float r0s = 0.f, r1s = 0.f;
#pragma unroll
        for (int j = 0; j < 8; j++) {
            float e0 = __expf(s_[j][0] - m0n);
            float e1 = __expf(s_[j][1] - m0n);
            float e2 = __expf(s_[j][2] - m1n);
            float e3 = __expf(s_[j][3] - m1n);
            r0s += e0 + e1; r1s += e2 + e3;
            pa[j >> 1][(j & 1) ? 2 : 0] = pack2f(e0, e1);
            pa[j >> 1][(j & 1) ? 3 : 1] = pack2f(e2, e3);
        }
        r0s += __shfl_xor_sync(0xffffffffu, r0s, 1);
        r0s += __shfl_xor_sync(0xffffffffu, r0s, 2);
        r1s += __shfl_xor_sync(0xffffffffu, r1s, 1);
        r1s += __shfl_xor_sync(0xffffffffu, r1s, 2);
        l0 = l0 * c0 + r0s;
        l1 = l1 * c1 + r1s;
#pragma unroll
        for (int j = 0; j < 8; j++) {
            o_[j][0] *= c0; o_[j][1] *= c0;
            o_[j][2] *= c1; o_[j][3] *= c1;
        }

        // ---- O += P V (fp16) ----
#pragma unroll
        for (int s = 0; s < 4; s++) {
            uint32_t vb[8][2];
#pragma unroll
            for (int jj = 0; jj < 4; jj++) {
                uint32_t addr = smb + (kb + VH_OFF + (uint32_t)((16 * s + vkey_off) * KSTR
                                       + 16 * jj + vcol_off)) * 2;
                ldsm4t(addr, vb[2 * jj][0], vb[2 * jj][1], vb[2 * jj + 1][0], vb[2 * jj + 1][1]);
            }
#pragma unroll
            for (int j = 0; j < 8; j++) mma16816(o_[j], pa[s], vb[j]);
        }
    }

    // ---- epilogue ----
    const float inv0 = 1.0f / l0, inv1 = 1.0f / l1;
    const int r0g = wr0 + g, r1g = wr0 + g + 8;
#pragma unroll
    for (int j = 0; j < 8; j++) {
        float2 v0 = make_float2(o_[j][0] * inv0, o_[j][1] * inv0);
        float2 v1 = make_float2(o_[j][2] * inv1, o_[j][3] * inv1);
        *(float2*)&Ob[(size_t)r0g * HD + 8 * j + 2 * tg] = v0;
        *(float2*)&Ob[(size_t)r1g * HD + 8 * j + 2 * tg] = v1;
    }
}

// ---------------------------------------------------------------------------
extern "C" void kernel_launch(void* const* d_in, const int* in_sizes, int n_in,
                              void* d_out, int out_size)
{
    const float* Q = (const float*)d_in[0];
    const float* K = (const float*)d_in[1];
    const float* V = (const float*)d_in[2];
    float*       O = (float*)d_out;

    const int n4 = BATCH * LSEQ * HD / 4;                 // 262144 float4s
    prep_kernel<<<n4 / 256, 256>>>((const float4*)Q, (const float4*)K, (const float4*)V);

    cudaFuncSetAttribute(attn_mma, cudaFuncAttributeMaxDynamicSharedMemorySize, SMEM_BYTES);
    dim3 grid(LSEQ / BM, BATCH);
    attn_mma<<<grid, NTHREADS, SMEM_BYTES>>>(O);
}

// round 5
// speedup vs baseline: 4.5031x; 1.0066x over previous
#include <cuda_runtime.h>
#include <cuda_fp16.h>
#include <cstdint>

// ============================================================================
// Flash attention via mma.sync.m16n8k16 (fp16 in, fp32 accum), sm_103 base ISA.
// B=4, L=4096, D=64.  S = Q K^T in 3xFP16 (compensated), online softmax,
// O = P V in fp16.  Prepass converts fp32 -> fp16 hi/resid once.
// R5: 2 CTAs/SM (regs<=128, smem 83KB, Q staged through pipeline buffers),
//     3-stage cp.async pipeline with a single __syncthreads per tile.
// ============================================================================

#define LSEQ 4096
#define BATCH 4
#define HD 64
#define BM 128
#define BN 64
#define NTILES (LSEQ / BN)     // 64
#define NTHREADS 256
#define QSTR 72                // padded smem row stride (halfs): conflict-free ldmatrix
#define KSTR 72

// smem: 3 pipeline stages, each {kh, kr, vh} of [BN][KSTR] halfs.
#define TILE_HALFS (BN * KSTR)            // 4608
#define STAGE_HALFS (3 * TILE_HALFS)      // 13824
#define KH_OFF 0
#define KR_OFF TILE_HALFS
#define VH_OFF (2 * TILE_HALFS)
#define NSTAGES 3
#define SMEM_BYTES (NSTAGES * STAGE_HALFS * 2)   // 82944 B
// Q staging (preamble only, overwritten by pipeline afterwards)
#define QH_S 0
#define QR_S (BM * QSTR)                  // 9216 halfs; QH+QR = 36864 B <= 82944 B

// fp16 scratch (converted once per run by prep_kernel)
__device__ __align__(16) __half g_qh[BATCH * LSEQ * HD];
__device__ __align__(16) __half g_qr[BATCH * LSEQ * HD];
__device__ __align__(16) __half g_kh[BATCH * LSEQ * HD];
__device__ __align__(16) __half g_kr[BATCH * LSEQ * HD];
__device__ __align__(16) __half g_vh[BATCH * LSEQ * HD];

// ---------------------------------------------------------------------------
// helpers
// ---------------------------------------------------------------------------
__device__ __forceinline__ uint32_t smem_u32(const void* p) {
    uint32_t a;
    asm("{ .reg .u64 t; cvta.to.shared.u64 t, %1; cvt.u32.u64 %0, t; }" : "=r"(a) : "l"(p));
    return a;
}
__device__ __forceinline__ void cp16(uint32_t dst, const void* src) {
    asm volatile("cp.async.ca.shared.global [%0], [%1], 16;" :: "r"(dst), "l"(src));
}
#define CP_COMMIT() asm volatile("cp.async.commit_group;" ::: "memory")
#define CP_WAIT(n)  asm volatile("cp.async.wait_group %0;" :: "n"(n) : "memory")

__device__ __forceinline__ void ldsm4(uint32_t addr, uint32_t& r0, uint32_t& r1,
                                      uint32_t& r2, uint32_t& r3) {
    asm volatile("ldmatrix.sync.aligned.m8n8.x4.shared.b16 {%0,%1,%2,%3}, [%4];"
                 : "=r"(r0), "=r"(r1), "=r"(r2), "=r"(r3) : "r"(addr));
}
__device__ __forceinline__ void ldsm4t(uint32_t addr, uint32_t& r0, uint32_t& r1,
                                       uint32_t& r2, uint32_t& r3) {
    asm volatile("ldmatrix.sync.aligned.m8n8.x4.trans.shared.b16 {%0,%1,%2,%3}, [%4];"
                 : "=r"(r0), "=r"(r1), "=r"(r2), "=r"(r3) : "r"(addr));
}
__device__ __forceinline__ void mma16816(float* c, const uint32_t* a, const uint32_t* b) {
    asm volatile("mma.sync.aligned.m16n8k16.row.col.f32.f16.f16.f32 "
                 "{%0,%1,%2,%3}, {%4,%5,%6,%7}, {%8,%9}, {%0,%1,%2,%3};"
                 : "+f"(c[0]), "+f"(c[1]), "+f"(c[2]), "+f"(c[3])
                 : "r"(a[0]), "r"(a[1]), "r"(a[2]), "r"(a[3]), "r"(b[0]), "r"(b[1]));
}
__device__ __forceinline__ uint32_t packh(__half a, __half b) {
    __half2 h = __halves2half2(a, b);
    return *(uint32_t*)&h;
}
__device__ __forceinline__ uint32_t pack2f(float a, float b) {
    __half2 h = __floats2half2_rn(a, b);
    return *(uint32_t*)&h;
}

// ---------------------------------------------------------------------------
// prepass: fp32 -> fp16 high + residual (Q, K), fp16 (V)
// ---------------------------------------------------------------------------
__global__ void prep_kernel(const float4* __restrict__ Q, const float4* __restrict__ K,
                            const float4* __restrict__ V) {
    int i = blockIdx.x * blockDim.x + threadIdx.x;   // float4 index
    float4 q = Q[i], k = K[i], v = V[i];

    __half qhx = __float2half_rn(q.x), qhy = __float2half_rn(q.y),
           qhz = __float2half_rn(q.z), qhw = __float2half_rn(q.w);
    __half qrx = __float2half_rn(q.x - __half2float(qhx)),
           qry = __float2half_rn(q.y - __half2float(qhy)),
           qrz = __float2half_rn(q.z - __half2float(qhz)),
           qrw = __float2half_rn(q.w - __half2float(qhw));
    ((uint2*)g_qh)[i] = make_uint2(packh(qhx, qhy), packh(qhz, qhw));
    ((uint2*)g_qr)[i] = make_uint2(packh(qrx, qry), packh(qrz, qrw));

    __half khx = __float2half_rn(k.x), khy = __float2half_rn(k.y),
           khz = __float2half_rn(k.z), khw = __float2half_rn(k.w);
    __half krx = __float2half_rn(k.x - __half2float(khx)),
           kry = __float2half_rn(k.y - __half2float(khy)),
           krz = __float2half_rn(k.z - __half2float(khz)),
           krw = __float2half_rn(k.w - __half2float(khw));
    ((uint2*)g_kh)[i] = make_uint2(packh(khx, khy), packh(khz, khw));
    ((uint2*)g_kr)[i] = make_uint2(packh(krx, kry), packh(krz, krw));

    ((uint2*)g_vh)[i] = make_uint2(pack2f(v.x, v.y), pack2f(v.z, v.w));
}

// ---------------------------------------------------------------------------
// main kernel
// ---------------------------------------------------------------------------
__device__ __forceinline__ void issue_tile(uint32_t smb, int stage, int t, int tid,
                                           const __half* kh_g, const __half* kr_g,
                                           const __half* vh_g) {
    const int base = stage * STAGE_HALFS;
    const __half* ks = kh_g + (size_t)t * BN * HD;
    const __half* rs = kr_g + (size_t)t * BN * HD;
    const __half* vs = vh_g + (size_t)t * BN * HD;
#pragma unroll
    for (int i = 0; i < 2; i++) {
        int cid = tid + i * NTHREADS;          // 0..511
        int r = cid >> 3, c = cid & 7;
        uint32_t d = (uint32_t)(r * KSTR * 2 + c * 16);
        const size_t so = (size_t)r * HD + c * 8;
        cp16(smb + (uint32_t)(base + KH_OFF) * 2 + d, ks + so);
        cp16(smb + (uint32_t)(base + KR_OFF) * 2 + d, rs + so);
        cp16(smb + (uint32_t)(base + VH_OFF) * 2 + d, vs + so);
    }
}

__global__ __launch_bounds__(NTHREADS, 2)
void attn_mma(float* __restrict__ O) {
    extern __shared__ __half sh[];
    const uint32_t smb = smem_u32(sh);
    const int tid = threadIdx.x, lane = tid & 31, wid = tid >> 5;
    const int g = lane >> 2, tg = lane & 3;
    const int wr0 = wid * 16;
    const int b = blockIdx.y, row0 = blockIdx.x * BM;

    const __half* qh_g = g_qh + (size_t)(b * LSEQ + row0) * HD;
    const __half* qr_g = g_qr + (size_t)(b * LSEQ + row0) * HD;
    const __half* kh_g = g_kh + (size_t)b * LSEQ * HD;
    const __half* kr_g = g_kr + (size_t)b * LSEQ * HD;
    const __half* vh_g = g_vh + (size_t)b * LSEQ * HD;
    float* Ob = O + (size_t)(b * LSEQ + row0) * HD;

    // ---- preamble: stage Q through the pipeline buffer area, pull to regs ----
#pragma unroll
    for (int i = 0; i < 4; i++) {
        int cid = tid + i * NTHREADS;          // 0..1023
        int r = cid >> 3, c = cid & 7;
        const size_t so = (size_t)r * HD + c * 8;
        cp16(smb + (uint32_t)(QH_S + r * QSTR) * 2 + c * 16, qh_g + so);
        cp16(smb + (uint32_t)(QR_S + r * QSTR) * 2 + c * 16, qr_g + so);
    }
    CP_COMMIT();
    CP_WAIT(0);
    __syncthreads();

    uint32_t qh[4][4], qr[4][4];
    {
        const int arow = wr0 + (lane & 15);
        const int koff = (lane >> 4) << 3;
#pragma unroll
        for (int s = 0; s < 4; s++) {
            uint32_t a1 = smb + (uint32_t)(QH_S + arow * QSTR + 16 * s + koff) * 2;
            uint32_t a2 = smb + (uint32_t)(QR_S + arow * QSTR + 16 * s + koff) * 2;
            ldsm4(a1, qh[s][0], qh[s][1], qh[s][2], qh[s][3]);
            ldsm4(a2, qr[s][0], qr[s][1], qr[s][2], qr[s][3]);
        }
    }
    __syncthreads();   // all warps have their Q frags; buffers can be overwritten

    // ---- pipeline prologue: tiles 0 and 1 in flight ----
    issue_tile(smb, 0, 0, tid, kh_g, kr_g, vh_g);
    CP_COMMIT();
    issue_tile(smb, 1, 1, tid, kh_g, kr_g, vh_g);
    CP_COMMIT();

    float o_[8][4];
#pragma unroll
    for (int j = 0; j < 8; j++)
#pragma unroll
        for (int q = 0; q < 4; q++) o_[j][q] = 0.f;
    float m0 = -1e30f, m1 = -1e30f, l0 = 0.f, l1 = 0.f;

    // per-lane ldmatrix source offsets (within a stage, halfs)
    const int krow_off = (lane & 7) + ((lane >> 4) << 3);   // + 16*jj
    const int kcol_off = (lane & 8);                        // + 16*s
    const int vkey_off = (lane & 7) + (lane & 8);           // + 16*s
    const int vcol_off = (lane >> 4) << 3;                  // + 16*jj

    int stage = 0, stage2 = 2;   // stage = t%3, stage2 = (t+2)%3

    for (int t = 0; t < NTILES; t++) {
        // tile t resident (group t complete; group t+1 may still be in flight)
        if (t + 1 < NTILES) { CP_WAIT(1); } else { CP_WAIT(0); }
        __syncthreads();   // tile t visible to all; readers of tile t-1 done

        if (t + 2 < NTILES) {
            issue_tile(smb, stage2, t + 2, tid, kh_g, kr_g, vh_g);
            CP_COMMIT();
        }

        const uint32_t kb = (uint32_t)(stage * STAGE_HALFS);

        // ---- S = Q K^T (3xFP16) ----
        float s_[8][4];
#pragma unroll
        for (int j = 0; j < 8; j++)
#pragma unroll
            for (int q = 0; q < 4; q++) s_[j][q] = 0.f;

#pragma unroll
        for (int s = 0; s < 4; s++) {
            uint32_t bb[8][2];
#pragma unroll
            for (int jj = 0; jj < 4; jj++) {
                uint32_t addr = smb + (kb + KH_OFF + (uint32_t)((16 * jj + krow_off) * KSTR
                                       + 16 * s + kcol_off)) * 2;
                ldsm4(addr, bb[2 * jj][0], bb[2 * jj][1], bb[2 * jj + 1][0], bb[2 * jj + 1][1]);
            }
#pragma unroll
            for (int j = 0; j < 8; j++) {
                mma16816(s_[j], qh[s], bb[j]);
                mma16816(s_[j], qr[s], bb[j]);
            }
#pragma unroll
            for (int jj = 0; jj < 4; jj++) {
                uint32_t addr = smb + (kb + KR_OFF + (uint32_t)((16 * jj + krow_off) * KSTR
                                       + 16 * s + kcol_off)) * 2;
                ldsm4(addr, bb[2 * jj][0], bb[2 * jj][1], bb[2 * jj + 1][0], bb[2 * jj + 1][1]);
            }
#pragma unroll
            for (int j = 0; j < 8; j++) mma16816(s_[j], qh[s], bb[j]);
        }

        // ---- online softmax (in-warp; rows g and g+8 of this warp) ----
        float m0t = s_[0][0], m1t = s_[0][2];
#pragma unroll
        for (int j = 0; j < 8; j++) {
            m0t = fmaxf(m0t, fmaxf(s_[j][0], s_[j][1]));
            m1t = fmaxf(m1t, fmaxf(s_[j][2], s_[j][3]));
        }
        m0t = fmaxf(m0t, __shfl_xor_sync(0xffffffffu, m0t, 1));
        m0t = fmaxf(m0t, __shfl_xor_sync(0xffffffffu, m0t, 2));
        m1t = fmaxf(m1t, __shfl_xor_sync(0xffffffffu, m1t, 1));
        m1t = fmaxf(m1t, __shfl_xor_sync(0xffffffffu, m1t, 2));
        const float m0n = fmaxf(m0, m0t), m1n = fmaxf(m1, m1t);
        const float c0 = __expf(m0 - m0n), c1 = __expf(m1 - m1n);
        m0 = m0n; m1 = m1n;

        uint32_t pa[4][4];
        float r0s = 0.f, r1s = 0.f;
#pragma unroll
        for (int j = 0; j < 8; j++) {
            float e0 = __expf(s_[j][0] - m0n);
            float e1 = __expf(s_[j][1] - m0n);
            float e2 = __expf(s_[j][2] - m1n);
            float e3 = __expf(s_[j][3] - m1n);
            r0s += e0 + e1; r1s += e2 + e3;
            pa[j >> 1][(j & 1) ? 2 : 0] = pack2f(e0, e1);
            pa[j >> 1][(j & 1) ? 3 : 1] = pack2f(e2, e3);
        }
        r0s += __shfl_xor_sync(0xffffffffu, r0s, 1);
        r0s += __shfl_xor_sync(0xffffffffu, r0s, 2);
        r1s += __shfl_xor_sync(0xffffffffu, r1s, 1);
        r1s += __shfl_xor_sync(0xffffffffu, r1s, 2);
        l0 = l0 * c0 + r0s;
        l1 = l1 * c1 + r1s;
#pragma unroll
        for (int j = 0; j < 8; j++) {
            o_[j][0] *= c0; o_[j][1] *= c0;
            o_[j][2] *= c1; o_[j][3] *= c1;
        }

        // ---- O += P V (fp16) ----
#pragma unroll
        for (int s = 0; s < 4; s++) {
            uint32_t vb[8][2];
#pragma unroll
            for (int jj = 0; jj < 4; jj++) {
                uint32_t addr = smb + (kb + VH_OFF + (uint32_t)((16 * s + vkey_off) * KSTR
                                       + 16 * jj + vcol_off)) * 2;
                ldsm4t(addr, vb[2 * jj][0], vb[2 * jj][1], vb[2 * jj + 1][0], vb[2 * jj + 1][1]);
            }
#pragma unroll
            for (int j = 0; j < 8; j++) mma16816(o_[j], pa[s], vb[j]);
        }

        stage = (stage == 2) ? 0 : stage + 1;
        stage2 = (stage2 == 2) ? 0 : stage2 + 1;
    }

    // ---- epilogue ----
    const float inv0 = 1.0f / l0, inv1 = 1.0f / l1;
    const int r0g = wr0 + g, r1g = wr0 + g + 8;
#pragma unroll
    for (int j = 0; j < 8; j++) {
        float2 v0 = make_float2(o_[j][0] * inv0, o_[j][1] * inv0);
        float2 v1 = make_float2(o_[j][2] * inv1, o_[j][3] * inv1);
        *(float2*)&Ob[(size_t)r0g * HD + 8 * j + 2 * tg] = v0;
        *(float2*)&Ob[(size_t)r1g * HD + 8 * j + 2 * tg] = v1;
    }
}

// ---------------------------------------------------------------------------
extern "C" void kernel_launch(void* const* d_in, const int* in_sizes, int n_in,
                              void* d_out, int out_size)
{
    const float* Q = (const float*)d_in[0];
    const float* K = (const float*)d_in[1];
    const float* V = (const float*)d_in[2];
    float*       O = (float*)d_out;

    const int n4 = BATCH * LSEQ * HD / 4;                 // 262144 float4s
    prep_kernel<<<n4 / 256, 256>>>((const float4*)Q, (const float4*)K, (const float4*)V);

    cudaFuncSetAttribute(attn_mma, cudaFuncAttributeMaxDynamicSharedMemorySize, SMEM_BYTES);
    dim3 grid(LSEQ / BM, BATCH);
    attn_mma<<<grid, NTHREADS, SMEM_BYTES>>>(O);
}